// round 7
// baseline (speedup 1.0000x reference)
#include <cuda_runtime.h>
#include <cuda_bf16.h>
#include <stdint.h>

#define NROW 4096
#define DIM  1024
#define NT   256
#define RS   40          // padded smem row stride (bf16 elems) for conflict-free ldmatrix

// Static device scratch (no runtime allocation allowed).
__device__ __nv_bfloat16 g_Xb[(size_t)NROW * DIM];   // 8 MB normalized embeddings (bf16)
__device__ float g_SIM[(size_t)NROW * NROW];         // 64 MB similarity matrix
__device__ unsigned char g_cls[NROW];
__device__ float g_rowloss[NROW];

// Monotone fp32 <-> uint32 key (ascending order preserved)
__device__ __forceinline__ unsigned int f2k(float f) {
    unsigned int u = __float_as_uint(f);
    return (u & 0x80000000u) ? ~u : (u | 0x80000000u);
}
__device__ __forceinline__ float k2f(unsigned int k) {
    unsigned int u = (k & 0x80000000u) ? (k & 0x7FFFFFFFu) : ~k;
    return __uint_as_float(u);
}

// ---------------------------------------------------------------------------
// Classes: reference declares int64 targets, but JAX without x64 emits int32.
// Sniff layout: if ALL odd int32 words are zero -> little-endian int64.
__global__ __launch_bounds__(1024) void cls_kernel(const int* __restrict__ tgt32) {
    __shared__ int s_any;
    const int t = threadIdx.x;
    if (t == 0) s_any = 0;
    __syncthreads();
    int any = 0;
    for (int j = t; j < NROW / 2; j += 1024)
        any |= (tgt32[2 * j + 1] != 0);
    if (any) atomicOr(&s_any, 1);
    __syncthreads();
    const bool is64 = (s_any == 0);
    for (int i = t; i < NROW; i += 1024)
        g_cls[i] = (unsigned char)(is64 ? tgt32[2 * i] : tgt32[i]);
}

// ---------------------------------------------------------------------------
// Single-pass normalize: each thread owns one float4 of the row.
__global__ __launch_bounds__(256) void normalize_kernel(const float* __restrict__ emb) {
    const int i = blockIdx.x;
    const int t = threadIdx.x;
    const int lane = t & 31;
    const int wid  = t >> 5;
    __shared__ float s[8];

    float4 v = *(const float4*)(emb + (size_t)i * DIM + t * 4);
    float ss = v.x * v.x + v.y * v.y + v.z * v.z + v.w * v.w;
#pragma unroll
    for (int o = 16; o > 0; o >>= 1) ss += __shfl_xor_sync(0xFFFFFFFFu, ss, o);
    if (lane == 0) s[wid] = ss;
    __syncthreads();
    float tot = 0.f;
#pragma unroll
    for (int w = 0; w < 8; w++) tot += s[w];
    const float norm = fmaxf(sqrtf(tot), 1e-12f);

    unsigned int u0 = (unsigned int)__bfloat16_as_ushort(__float2bfloat16(v.x / norm));
    unsigned int u1 = (unsigned int)__bfloat16_as_ushort(__float2bfloat16(v.y / norm));
    unsigned int u2 = (unsigned int)__bfloat16_as_ushort(__float2bfloat16(v.z / norm));
    unsigned int u3 = (unsigned int)__bfloat16_as_ushort(__float2bfloat16(v.w / norm));
    uint2 pk;
    pk.x = u0 | (u1 << 16);
    pk.y = u2 | (u3 << 16);
    *(uint2*)(g_Xb + (size_t)i * DIM + t * 4) = pk;
}

// ---------------------------------------------------------------------------
// SIM = X * X^T in bf16 tensor cores. SYMMETRIC: only lower-triangular blocks
// (528 of 1024) are computed; off-diagonal blocks store their transpose too,
// staged through smem so all global stores stay coalesced.
__device__ __forceinline__ void cp16(unsigned int smem_dst, const void* gsrc) {
    asm volatile("cp.async.cg.shared.global [%0], [%1], 16;\n" :: "r"(smem_dst), "l"(gsrc));
}
__device__ __forceinline__ void cp_commit() { asm volatile("cp.async.commit_group;\n"); }
__device__ __forceinline__ void cp_wait0() { asm volatile("cp.async.wait_group 0;\n"); }

__global__ __launch_bounds__(256) void gemm_kernel() {
    __shared__ __align__(16) char smbuf[2 * 128 * RS * 2 * 2];
    typedef __nv_bfloat16 Tile[128][RS];
    Tile* sA = reinterpret_cast<Tile*>(smbuf);
    Tile* sB = reinterpret_cast<Tile*>(smbuf + 2 * 128 * RS * 2);
    float (*tr)[132] = reinterpret_cast<float (*)[132]>(smbuf);

    const int t    = threadIdx.x;
    const int lane = t & 31;
    const int wid  = t >> 5;
    const int wm   = (wid >> 2) * 64;
    const int wn   = (wid & 3) * 32;

    const int b = blockIdx.x;
    int p = (int)((sqrtf(8.f * (float)b + 1.f) - 1.f) * 0.5f);
    while ((p + 1) * (p + 2) / 2 <= b) p++;
    while (p * (p + 1) / 2 > b) p--;
    const int q  = b - p * (p + 1) / 2;
    const int bi = p * 128;
    const int bj = q * 128;

    float acc[4][4][4];
#pragma unroll
    for (int mt = 0; mt < 4; mt++)
#pragma unroll
        for (int nt = 0; nt < 4; nt++)
#pragma unroll
            for (int r = 0; r < 4; r++) acc[mt][nt][r] = 0.f;

    auto load_stage = [&](int buf, int k0) {
#pragma unroll
        for (int c = t; c < 512; c += 256) {
            int row = c >> 2, off = (c & 3) * 8;
            cp16((unsigned int)__cvta_generic_to_shared(&sA[buf][row][off]),
                 g_Xb + (size_t)(bi + row) * DIM + k0 + off);
            cp16((unsigned int)__cvta_generic_to_shared(&sB[buf][row][off]),
                 g_Xb + (size_t)(bj + row) * DIM + k0 + off);
        }
    };

    load_stage(0, 0);
    cp_commit();
    cp_wait0();
    __syncthreads();

    for (int s = 0; s < DIM / 32; s++) {
        const int cbuf = s & 1;
        if (s + 1 < DIM / 32) {
            load_stage((s + 1) & 1, (s + 1) * 32);
            cp_commit();
        }
#pragma unroll
        for (int ks = 0; ks < 2; ks++) {
            unsigned int a[4][4], bb[4][2];
#pragma unroll
            for (int mt = 0; mt < 4; mt++) {
                unsigned int addr = (unsigned int)__cvta_generic_to_shared(
                    &sA[cbuf][wm + mt * 16 + (lane & 15)][ks * 16 + (lane >> 4) * 8]);
                asm volatile("ldmatrix.sync.aligned.m8n8.x4.shared.b16 {%0,%1,%2,%3}, [%4];"
                             : "=r"(a[mt][0]), "=r"(a[mt][1]), "=r"(a[mt][2]), "=r"(a[mt][3])
                             : "r"(addr));
            }
#pragma unroll
            for (int nt = 0; nt < 4; nt++) {
                unsigned int addr = (unsigned int)__cvta_generic_to_shared(
                    &sB[cbuf][wn + nt * 8 + (lane & 7)][ks * 16 + ((lane >> 3) & 1) * 8]);
                asm volatile("ldmatrix.sync.aligned.m8n8.x2.shared.b16 {%0,%1}, [%2];"
                             : "=r"(bb[nt][0]), "=r"(bb[nt][1]) : "r"(addr));
            }
#pragma unroll
            for (int mt = 0; mt < 4; mt++)
#pragma unroll
                for (int nt = 0; nt < 4; nt++) {
                    asm volatile(
                        "mma.sync.aligned.m16n8k16.row.col.f32.bf16.bf16.f32 "
                        "{%0,%1,%2,%3},{%4,%5,%6,%7},{%8,%9},{%0,%1,%2,%3};"
                        : "+f"(acc[mt][nt][0]), "+f"(acc[mt][nt][1]),
                          "+f"(acc[mt][nt][2]), "+f"(acc[mt][nt][3])
                        : "r"(a[mt][0]), "r"(a[mt][1]), "r"(a[mt][2]), "r"(a[mt][3]),
                          "r"(bb[nt][0]), "r"(bb[nt][1]));
                }
        }
        if (s + 1 < DIM / 32) cp_wait0();
        __syncthreads();
    }

#pragma unroll
    for (int mt = 0; mt < 4; mt++) {
#pragma unroll
        for (int nt = 0; nt < 4; nt++) {
            int r0 = bi + wm + mt * 16 + (lane >> 2);
            int c0 = bj + wn + nt * 8 + (lane & 3) * 2;
            *(float2*)(g_SIM + (size_t)r0 * NROW + c0) =
                make_float2(acc[mt][nt][0], acc[mt][nt][1]);
            *(float2*)(g_SIM + (size_t)(r0 + 8) * NROW + c0) =
                make_float2(acc[mt][nt][2], acc[mt][nt][3]);
        }
    }

    if (p != q) {
        for (int cc = 0; cc < 4; cc++) {
            __syncthreads();
            if ((wid & 3) == cc) {
#pragma unroll
                for (int mt = 0; mt < 4; mt++)
#pragma unroll
                    for (int nt = 0; nt < 4; nt++) {
                        int r0 = wm + mt * 16 + (lane >> 2);
                        int c0 = nt * 8 + (lane & 3) * 2;
                        tr[c0    ][r0    ] = acc[mt][nt][0];
                        tr[c0 + 1][r0    ] = acc[mt][nt][1];
                        tr[c0    ][r0 + 8] = acc[mt][nt][2];
                        tr[c0 + 1][r0 + 8] = acc[mt][nt][3];
                    }
            }
            __syncthreads();
            const int c = t >> 3;
            const int r = (t & 7) * 16;
            float* dst = g_SIM + (size_t)(bj + cc * 32 + c) * NROW + bi + r;
#pragma unroll
            for (int k = 0; k < 4; k++)
                *(float4*)(dst + k * 4) = *(float4*)(&tr[c][r + k * 4]);
        }
    }
}

// ---------------------------------------------------------------------------
// Per-row loss v3: raw values + bitmasks in smem; 11-bit (2048-bin) first-round
// histogram fused into the load; then DIRECT candidate collection (quarter-octave
// bin holds ~150 keys); exact 8-bit radix fallback if candidates overflow.
__global__ __launch_bounds__(NT) void row_loss_kernel() {
    __shared__ float        s_v[NROW];       // 16 KB raw sims
    __shared__ unsigned int s_hist[2048];    // 8 KB
    __shared__ unsigned int s_cand[512];     // 2 KB
    __shared__ unsigned int s_negm[128];     // neg bitmask
    __shared__ unsigned int s_posm[128];     // pos-excl-self bitmask
    __shared__ unsigned int s_wtot[8];
    __shared__ float        s_red[8];
    __shared__ unsigned int sh_sel, sh_r, sh_h, sh_cnt, sh_key, sh_m;

    const int i    = blockIdx.x;
    const int t    = threadIdx.x;
    const int lane = t & 31;
    const int wid  = t >> 5;
    const unsigned char myc = g_cls[i];
    const float* row = g_SIM + (size_t)i * NROW;

    *(uint4*)&s_hist[t * 8]     = make_uint4(0, 0, 0, 0);
    *(uint4*)&s_hist[t * 8 + 4] = make_uint4(0, 0, 0, 0);
    if (t < 128) { s_negm[t] = 0; s_posm[t] = 0; }
    __syncthreads();

    // ---- load pass: s_v + bitmasks + 11-bit histogram + K + pos_max ----
    float pmax = -1e30f;
    int   kneg = 0;
#pragma unroll
    for (int c = 0; c < 4; c++) {
        const int j0 = (c * NT + t) * 4;
        float4 v4 = *(const float4*)(row + j0);
        uchar4 c4 = *(const uchar4*)(g_cls + j0);
        float vv[4] = {v4.x, v4.y, v4.z, v4.w};
        unsigned char cc[4] = {c4.x, c4.y, c4.z, c4.w};
        unsigned int nb = 0, pb = 0;
#pragma unroll
        for (int e = 0; e < 4; e++) {
            if (cc[e] != myc) {
                nb |= (1u << e);
                kneg++;
                atomicAdd(&s_hist[f2k(vv[e]) >> 21], 1u);
            } else if (j0 + e != i) {
                pb |= (1u << e);
                pmax = fmaxf(pmax, vv[e]);
            }
        }
        *(float4*)(s_v + j0) = v4;
        const int word = c * 32 + (t >> 3);
        const int shp  = (t & 7) * 4;
        if (nb) atomicOr(&s_negm[word], nb << shp);
        if (pb) atomicOr(&s_posm[word], pb << shp);
    }
#pragma unroll
    for (int o = 16; o > 0; o >>= 1) {
        kneg += __shfl_xor_sync(0xFFFFFFFFu, kneg, o);
        pmax  = fmaxf(pmax, __shfl_xor_sync(0xFFFFFFFFu, pmax, o));
    }
    if (lane == 0) { s_wtot[wid] = (unsigned int)kneg; s_red[wid] = pmax; }
    __syncthreads();
    unsigned int K = 0; float pm = -1e30f;
#pragma unroll
    for (int w = 0; w < 8; w++) { K += s_wtot[w]; pm = fmaxf(pm, s_red[w]); }
    const int drop = max((int)floorf((float)K * 0.05f), 1);
    const unsigned int r0full = (unsigned int)(drop + 1);

    // ---- select bucket among 2048 bins (thread t owns bins t*8..t*8+7) ----
    {
        unsigned int loc[8], total = 0;
#pragma unroll
        for (int e = 0; e < 8; e++) { loc[e] = s_hist[t * 8 + e]; total += loc[e]; }
        unsigned int suf = total;
#pragma unroll
        for (int o = 1; o < 32; o <<= 1) {
            const unsigned int w = __shfl_down_sync(0xFFFFFFFFu, suf, o);
            if (lane + o < 32) suf += w;
        }
        if (lane == 0) s_wtot[wid] = suf;
        __syncthreads();
#pragma unroll
        for (int w = 0; w < 8; w++) if (w > wid) suf += s_wtot[w];
        unsigned int before = 0;
#pragma unroll
        for (int e = 0; e < 8; e++) {
            const unsigned int sb = suf - before;       // sum of bins >= t*8+e
            const unsigned int h  = loc[e];
            if (sb >= r0full && (sb - h) < r0full) {
                sh_sel = (unsigned int)(t * 8 + e);
                sh_r   = r0full - (sb - h);
                sh_h   = h;
            }
            before += h;
        }
        __syncthreads();
    }
    const unsigned int prefix11 = sh_sel;    // top 11 bits of threshold key
    unsigned int r = sh_r;
    __syncthreads();

    // ---- candidate collection: negatives whose key shares the 11-bit prefix ----
    if (t == 0) sh_cnt = 0;
    __syncthreads();
#pragma unroll
    for (int c = 0; c < 4; c++) {
        const int j0 = (c * NT + t) * 4;
        float4 v4 = *(const float4*)(s_v + j0);
        float vv[4] = {v4.x, v4.y, v4.z, v4.w};
        const unsigned int nn = (s_negm[c * 32 + (t >> 3)] >> ((t & 7) * 4)) & 0xFu;
#pragma unroll
        for (int e = 0; e < 4; e++) {
            if ((nn >> e) & 1u) {
                const unsigned int k = f2k(vv[e]);
                if ((k >> 21) == prefix11) {
                    unsigned int pslot = atomicAdd(&sh_cnt, 1u);
                    if (pslot < 512) s_cand[pslot] = k;
                }
            }
        }
    }
    __syncthreads();

    if (sh_cnt <= 512u) {
        // exact rank-select among C candidates
        const unsigned int C = sh_cnt;
        for (int idx = t; idx < (int)C; idx += NT) {
            const unsigned int k = s_cand[idx];
            unsigned int cg = 0, ce = 0;
            for (unsigned int j = 0; j < C; j++) {
                const unsigned int kj = s_cand[j];
                cg += (kj > k); ce += (kj == k);
            }
            if (cg < r && r <= cg + ce) {
                sh_key = k;
                sh_m   = ce + 1u - (r - cg);
            }
        }
        __syncthreads();
    } else {
        // exact fallback: full 8-bit radix select from scratch
        unsigned int rr = r0full, prefix = 0;
        for (int round = 0; round < 4; round++) {
            const int shift = 24 - 8 * round;
            s_hist[t] = 0;
            __syncthreads();
#pragma unroll
            for (int c = 0; c < 4; c++) {
                const int j0 = (c * NT + t) * 4;
                float4 v4 = *(const float4*)(s_v + j0);
                float vv[4] = {v4.x, v4.y, v4.z, v4.w};
                const unsigned int nn = (s_negm[c * 32 + (t >> 3)] >> ((t & 7) * 4)) & 0xFu;
#pragma unroll
                for (int e = 0; e < 4; e++) {
                    if ((nn >> e) & 1u) {
                        const unsigned int k = f2k(vv[e]);
                        if (round == 0 || (k >> (shift + 8)) == prefix)
                            atomicAdd(&s_hist[(k >> shift) & 255u], 1u);
                    }
                }
            }
            __syncthreads();
            {
                const unsigned int h = s_hist[t];
                unsigned int suf = h;
#pragma unroll
                for (int o = 1; o < 32; o <<= 1) {
                    const unsigned int w = __shfl_down_sync(0xFFFFFFFFu, suf, o);
                    if (lane + o < 32) suf += w;
                }
                if (lane == 0) s_wtot[wid] = suf;
                __syncthreads();
#pragma unroll
                for (int w = 0; w < 8; w++) if (w > wid) suf += s_wtot[w];
                if (suf >= rr && (suf - h) < rr) {
                    sh_sel = (unsigned int)t;
                    sh_r   = rr - (suf - h);
                    sh_h   = h;
                }
                __syncthreads();
            }
            prefix = (prefix << 8) | sh_sel;
            rr = sh_r;
            __syncthreads();
        }
        if (t == 0) { sh_key = prefix; sh_m = sh_h + 1u - sh_r; }
        __syncthreads();
    }

    const float T = k2f(sh_key);                 // == neg_thresh exactly
    const int   m = (int)sh_m;                   // # kept negatives equal to T

    // ---- fused final pass: pos_loss + neg_sum ----
    const float thr   = T + 0.1f;
    const float lower = fmaxf(0.6f, pm) - 0.1f;
    float ploss = 0.f, ns = 0.f;
#pragma unroll
    for (int c = 0; c < 4; c++) {
        const int j0 = (c * NT + t) * 4;
        float4 v4 = *(const float4*)(s_v + j0);
        float vv[4] = {v4.x, v4.y, v4.z, v4.w};
        const unsigned int mw = s_negm[c * 32 + (t >> 3)];
        const unsigned int pw = s_posm[c * 32 + (t >> 3)];
        const unsigned int nn = (mw >> ((t & 7) * 4)) & 0xFu;
        const unsigned int pp = (pw >> ((t & 7) * 4)) & 0xFu;
#pragma unroll
        for (int e = 0; e < 4; e++) {
            const float v = vv[e];
            if (((nn >> e) & 1u) && v < T && v > lower) ns += v;
            if (((pp >> e) & 1u) && v < thr) ploss += 1.0f - v;
        }
    }
#pragma unroll
    for (int o = 16; o > 0; o >>= 1) {
        ploss += __shfl_xor_sync(0xFFFFFFFFu, ploss, o);
        ns    += __shfl_xor_sync(0xFFFFFFFFu, ns, o);
    }
    if (lane == 0) { s_red[wid] = ploss; s_wtot[wid] = __float_as_uint(ns); }
    __syncthreads();

    if (t == 0) {
        float pl = 0.f, nss = 0.f;
#pragma unroll
        for (int w = 0; w < 8; w++) { pl += s_red[w]; nss += __uint_as_float(s_wtot[w]); }
        float loss = 0.f;
        if (pm > -1e29f) {                       // has_pos
            loss = pl + nss;
            if (T > lower) loss += (float)m * T; // ties at threshold (kept copies)
        }
        g_rowloss[i] = loss;
    }
}

// ---------------------------------------------------------------------------
__global__ void finalize_kernel(float* __restrict__ out) {
    __shared__ float s[1024];
    int t = threadIdx.x;
    float a = 0.f;
    for (int j = t; j < NROW; j += 1024) a += g_rowloss[j];
    s[t] = a; __syncthreads();
    for (int o = 512; o > 0; o >>= 1) { if (t < o) s[t] += s[t + o]; __syncthreads(); }
    if (t == 0) out[0] = s[0] / (float)NROW;
}

// ---------------------------------------------------------------------------
extern "C" void kernel_launch(void* const* d_in, const int* in_sizes, int n_in,
                              void* d_out, int out_size) {
    const float* emb   = (const float*)d_in[0];
    const int*   tgt32 = (const int*)d_in[1];
    float* out = (float*)d_out;

    cls_kernel<<<1, 1024>>>(tgt32);
    normalize_kernel<<<NROW, 256>>>(emb);
    gemm_kernel<<<528, 256>>>();
    row_loss_kernel<<<NROW, NT>>>();
    finalize_kernel<<<1, 1024>>>(out);
}

// round 8
// speedup vs baseline: 1.1282x; 1.1282x over previous
#include <cuda_runtime.h>
#include <cuda_bf16.h>
#include <stdint.h>

#define NROW 4096
#define DIM  1024
#define NT   256
#define RS   40          // padded smem row stride (bf16 elems) for conflict-free ldmatrix

// Static device scratch (no runtime allocation allowed).
__device__ __nv_bfloat16 g_Xb[(size_t)NROW * DIM];   // 8 MB normalized embeddings (bf16)
__device__ float g_SIM[(size_t)NROW * NROW];         // 64 MB similarity matrix
__device__ unsigned char g_cls[NROW];
__device__ float g_rowloss[NROW];

// Monotone fp32 <-> uint32 key (ascending order preserved)
__device__ __forceinline__ unsigned int f2k(float f) {
    unsigned int u = __float_as_uint(f);
    return (u & 0x80000000u) ? ~u : (u | 0x80000000u);
}
__device__ __forceinline__ float k2f(unsigned int k) {
    unsigned int u = (k & 0x80000000u) ? (k & 0x7FFFFFFFu) : ~k;
    return __uint_as_float(u);
}

// ---------------------------------------------------------------------------
// Classes: reference declares int64 targets, but JAX without x64 emits int32.
// Sniff layout: if ALL odd int32 words are zero -> little-endian int64.
__global__ __launch_bounds__(1024) void cls_kernel(const int* __restrict__ tgt32) {
    __shared__ int s_any;
    const int t = threadIdx.x;
    if (t == 0) s_any = 0;
    __syncthreads();
    int any = 0;
    for (int j = t; j < NROW / 2; j += 1024)
        any |= (tgt32[2 * j + 1] != 0);
    if (any) atomicOr(&s_any, 1);
    __syncthreads();
    const bool is64 = (s_any == 0);
    for (int i = t; i < NROW; i += 1024)
        g_cls[i] = (unsigned char)(is64 ? tgt32[2 * i] : tgt32[i]);
}

// ---------------------------------------------------------------------------
// Single-pass normalize: each thread owns one float4 of the row.
__global__ __launch_bounds__(256) void normalize_kernel(const float* __restrict__ emb) {
    const int i = blockIdx.x;
    const int t = threadIdx.x;
    const int lane = t & 31;
    const int wid  = t >> 5;
    __shared__ float s[8];

    float4 v = *(const float4*)(emb + (size_t)i * DIM + t * 4);
    float ss = v.x * v.x + v.y * v.y + v.z * v.z + v.w * v.w;
#pragma unroll
    for (int o = 16; o > 0; o >>= 1) ss += __shfl_xor_sync(0xFFFFFFFFu, ss, o);
    if (lane == 0) s[wid] = ss;
    __syncthreads();
    float tot = 0.f;
#pragma unroll
    for (int w = 0; w < 8; w++) tot += s[w];
    const float norm = fmaxf(sqrtf(tot), 1e-12f);

    unsigned int u0 = (unsigned int)__bfloat16_as_ushort(__float2bfloat16(v.x / norm));
    unsigned int u1 = (unsigned int)__bfloat16_as_ushort(__float2bfloat16(v.y / norm));
    unsigned int u2 = (unsigned int)__bfloat16_as_ushort(__float2bfloat16(v.z / norm));
    unsigned int u3 = (unsigned int)__bfloat16_as_ushort(__float2bfloat16(v.w / norm));
    uint2 pk;
    pk.x = u0 | (u1 << 16);
    pk.y = u2 | (u3 << 16);
    *(uint2*)(g_Xb + (size_t)i * DIM + t * 4) = pk;
}

// ---------------------------------------------------------------------------
// SIM = X * X^T in bf16 tensor cores. SYMMETRIC: only lower-triangular blocks
// (528 of 1024) are computed; off-diagonal blocks store their transpose too,
// staged through smem so all global stores stay coalesced.
__device__ __forceinline__ void cp16(unsigned int smem_dst, const void* gsrc) {
    asm volatile("cp.async.cg.shared.global [%0], [%1], 16;\n" :: "r"(smem_dst), "l"(gsrc));
}
__device__ __forceinline__ void cp_commit() { asm volatile("cp.async.commit_group;\n"); }
__device__ __forceinline__ void cp_wait0() { asm volatile("cp.async.wait_group 0;\n"); }

__global__ __launch_bounds__(256) void gemm_kernel() {
    __shared__ __align__(16) char smbuf[2 * 128 * RS * 2 * 2];
    typedef __nv_bfloat16 Tile[128][RS];
    Tile* sA = reinterpret_cast<Tile*>(smbuf);
    Tile* sB = reinterpret_cast<Tile*>(smbuf + 2 * 128 * RS * 2);
    float (*tr)[132] = reinterpret_cast<float (*)[132]>(smbuf);

    const int t    = threadIdx.x;
    const int lane = t & 31;
    const int wid  = t >> 5;
    const int wm   = (wid >> 2) * 64;
    const int wn   = (wid & 3) * 32;

    const int b = blockIdx.x;
    int p = (int)((sqrtf(8.f * (float)b + 1.f) - 1.f) * 0.5f);
    while ((p + 1) * (p + 2) / 2 <= b) p++;
    while (p * (p + 1) / 2 > b) p--;
    const int q  = b - p * (p + 1) / 2;
    const int bi = p * 128;
    const int bj = q * 128;

    float acc[4][4][4];
#pragma unroll
    for (int mt = 0; mt < 4; mt++)
#pragma unroll
        for (int nt = 0; nt < 4; nt++)
#pragma unroll
            for (int r = 0; r < 4; r++) acc[mt][nt][r] = 0.f;

    auto load_stage = [&](int buf, int k0) {
#pragma unroll
        for (int c = t; c < 512; c += 256) {
            int row = c >> 2, off = (c & 3) * 8;
            cp16((unsigned int)__cvta_generic_to_shared(&sA[buf][row][off]),
                 g_Xb + (size_t)(bi + row) * DIM + k0 + off);
            cp16((unsigned int)__cvta_generic_to_shared(&sB[buf][row][off]),
                 g_Xb + (size_t)(bj + row) * DIM + k0 + off);
        }
    };

    load_stage(0, 0);
    cp_commit();
    cp_wait0();
    __syncthreads();

    for (int s = 0; s < DIM / 32; s++) {
        const int cbuf = s & 1;
        if (s + 1 < DIM / 32) {
            load_stage((s + 1) & 1, (s + 1) * 32);
            cp_commit();
        }
#pragma unroll
        for (int ks = 0; ks < 2; ks++) {
            unsigned int a[4][4], bb[4][2];
#pragma unroll
            for (int mt = 0; mt < 4; mt++) {
                unsigned int addr = (unsigned int)__cvta_generic_to_shared(
                    &sA[cbuf][wm + mt * 16 + (lane & 15)][ks * 16 + (lane >> 4) * 8]);
                asm volatile("ldmatrix.sync.aligned.m8n8.x4.shared.b16 {%0,%1,%2,%3}, [%4];"
                             : "=r"(a[mt][0]), "=r"(a[mt][1]), "=r"(a[mt][2]), "=r"(a[mt][3])
                             : "r"(addr));
            }
#pragma unroll
            for (int nt = 0; nt < 4; nt++) {
                unsigned int addr = (unsigned int)__cvta_generic_to_shared(
                    &sB[cbuf][wn + nt * 8 + (lane & 7)][ks * 16 + ((lane >> 3) & 1) * 8]);
                asm volatile("ldmatrix.sync.aligned.m8n8.x2.shared.b16 {%0,%1}, [%2];"
                             : "=r"(bb[nt][0]), "=r"(bb[nt][1]) : "r"(addr));
            }
#pragma unroll
            for (int mt = 0; mt < 4; mt++)
#pragma unroll
                for (int nt = 0; nt < 4; nt++) {
                    asm volatile(
                        "mma.sync.aligned.m16n8k16.row.col.f32.bf16.bf16.f32 "
                        "{%0,%1,%2,%3},{%4,%5,%6,%7},{%8,%9},{%0,%1,%2,%3};"
                        : "+f"(acc[mt][nt][0]), "+f"(acc[mt][nt][1]),
                          "+f"(acc[mt][nt][2]), "+f"(acc[mt][nt][3])
                        : "r"(a[mt][0]), "r"(a[mt][1]), "r"(a[mt][2]), "r"(a[mt][3]),
                          "r"(bb[nt][0]), "r"(bb[nt][1]));
                }
        }
        if (s + 1 < DIM / 32) cp_wait0();
        __syncthreads();
    }

#pragma unroll
    for (int mt = 0; mt < 4; mt++) {
#pragma unroll
        for (int nt = 0; nt < 4; nt++) {
            int r0 = bi + wm + mt * 16 + (lane >> 2);
            int c0 = bj + wn + nt * 8 + (lane & 3) * 2;
            *(float2*)(g_SIM + (size_t)r0 * NROW + c0) =
                make_float2(acc[mt][nt][0], acc[mt][nt][1]);
            *(float2*)(g_SIM + (size_t)(r0 + 8) * NROW + c0) =
                make_float2(acc[mt][nt][2], acc[mt][nt][3]);
        }
    }

    if (p != q) {
        for (int cc = 0; cc < 4; cc++) {
            __syncthreads();
            if ((wid & 3) == cc) {
#pragma unroll
                for (int mt = 0; mt < 4; mt++)
#pragma unroll
                    for (int nt = 0; nt < 4; nt++) {
                        int r0 = wm + mt * 16 + (lane >> 2);
                        int c0 = nt * 8 + (lane & 3) * 2;
                        tr[c0    ][r0    ] = acc[mt][nt][0];
                        tr[c0 + 1][r0    ] = acc[mt][nt][1];
                        tr[c0    ][r0 + 8] = acc[mt][nt][2];
                        tr[c0 + 1][r0 + 8] = acc[mt][nt][3];
                    }
            }
            __syncthreads();
            const int c = t >> 3;
            const int r = (t & 7) * 16;
            float* dst = g_SIM + (size_t)(bj + cc * 32 + c) * NROW + bi + r;
#pragma unroll
            for (int k = 0; k < 4; k++)
                *(float4*)(dst + k * 4) = *(float4*)(&tr[c][r + k * 4]);
        }
    }
}

// ---------------------------------------------------------------------------
// Per-row loss (R6-proven version): pre-masked keys in smem, fused round-0
// histogram, round-1, candidate shortcut at 16-bit prefix, exact fallback.
__global__ __launch_bounds__(NT) void row_loss_kernel() {
    __shared__ unsigned int s_k[NROW];      // 16 KB
    __shared__ float        s_p[NROW];      // 16 KB
    __shared__ unsigned int s_hist[256];
    __shared__ unsigned int s_cand[256];
    __shared__ unsigned int s_wtot[8];
    __shared__ float        s_red[8];
    __shared__ unsigned int sh_sel, sh_r, sh_h, sh_cnt;
    __shared__ unsigned int sh_key, sh_m;

    const int i    = blockIdx.x;
    const int t    = threadIdx.x;
    const int lane = t & 31;
    const int wid  = t >> 5;
    const unsigned char myc = g_cls[i];
    const float* row = g_SIM + (size_t)i * NROW;

    s_hist[t] = 0;
    __syncthreads();

    // ---- load pass: fill s_k/s_p, round-0 histogram, K count, pos_max ----
    float pmax = -1e30f;
    int   kneg = 0;
#pragma unroll
    for (int c = 0; c < 4; c++) {
        const int j0 = (c * NT + t) * 4;
        float4 v4 = *(const float4*)(row + j0);
        uchar4 c4 = *(const uchar4*)(g_cls + j0);
        float vv[4] = {v4.x, v4.y, v4.z, v4.w};
        unsigned char cc[4] = {c4.x, c4.y, c4.z, c4.w};
        unsigned int kk[4];
        float        pp[4];
#pragma unroll
        for (int e = 0; e < 4; e++) {
            const int idx = j0 + e;
            if (cc[e] != myc) {
                const unsigned int key = f2k(vv[e]);
                kk[e] = key; pp[e] = -1e30f;
                kneg++;
                atomicAdd(&s_hist[key >> 24], 1u);
            } else {
                kk[e] = 0u;
                pp[e] = (idx != i) ? vv[e] : -1e30f;
                pmax = fmaxf(pmax, pp[e]);
            }
        }
        *(uint4*)(s_k + j0)  = make_uint4(kk[0], kk[1], kk[2], kk[3]);
        *(float4*)(s_p + j0) = make_float4(pp[0], pp[1], pp[2], pp[3]);
    }
#pragma unroll
    for (int o = 16; o > 0; o >>= 1) {
        kneg += __shfl_xor_sync(0xFFFFFFFFu, kneg, o);
        pmax  = fmaxf(pmax, __shfl_xor_sync(0xFFFFFFFFu, pmax, o));
    }
    if (lane == 0) { s_wtot[wid] = (unsigned int)kneg; s_red[wid] = pmax; }
    __syncthreads();
    unsigned int K = 0; float pm = -1e30f;
#pragma unroll
    for (int w = 0; w < 8; w++) { K += s_wtot[w]; pm = fmaxf(pm, s_red[w]); }
    const int drop = max((int)floorf((float)K * 0.05f), 1);
    unsigned int r = (unsigned int)(drop + 1);

    auto select_bucket = [&](unsigned int rr) {
        const unsigned int h = s_hist[t];
        unsigned int suf = h;
#pragma unroll
        for (int o = 1; o < 32; o <<= 1) {
            const unsigned int w = __shfl_down_sync(0xFFFFFFFFu, suf, o);
            if (lane + o < 32) suf += w;
        }
        if (lane == 0) s_wtot[wid] = suf;
        __syncthreads();
#pragma unroll
        for (int w = 0; w < 8; w++) if (w > wid) suf += s_wtot[w];
        if (suf >= rr && (suf - h) < rr) {
            sh_sel = (unsigned int)t;
            sh_r   = rr - (suf - h);
            sh_h   = h;
        }
        __syncthreads();
    };

    // ---- round 0 (hist already built) ----
    select_bucket(r);
    unsigned int prefix = sh_sel;
    r = sh_r;
    __syncthreads();

    // ---- round 1 ----
    s_hist[t] = 0;
    __syncthreads();
#pragma unroll
    for (int c = 0; c < 4; c++) {
        uint4 k4 = *(const uint4*)(s_k + (c * NT + t) * 4);
        unsigned int kk[4] = {k4.x, k4.y, k4.z, k4.w};
#pragma unroll
        for (int e = 0; e < 4; e++)
            if ((kk[e] >> 24) == prefix)
                atomicAdd(&s_hist[(kk[e] >> 16) & 255u], 1u);
    }
    __syncthreads();
    select_bucket(r);
    prefix = (prefix << 8) | sh_sel;
    r = sh_r;
    __syncthreads();

    // ---- candidate collection for low 16 bits ----
    if (t == 0) sh_cnt = 0;
    __syncthreads();
#pragma unroll
    for (int c = 0; c < 4; c++) {
        uint4 k4 = *(const uint4*)(s_k + (c * NT + t) * 4);
        unsigned int kk[4] = {k4.x, k4.y, k4.z, k4.w};
#pragma unroll
        for (int e = 0; e < 4; e++)
            if ((kk[e] >> 16) == prefix) {
                unsigned int pslot = atomicAdd(&sh_cnt, 1u);
                if (pslot < 256) s_cand[pslot] = kk[e];
            }
    }
    __syncthreads();

    if (sh_cnt <= 256u) {
        const unsigned int C = sh_cnt;
        if (t < (int)C) {
            const unsigned int k = s_cand[t];
            unsigned int cg = 0, ce = 0;
            for (unsigned int j = 0; j < C; j++) {
                const unsigned int kj = s_cand[j];
                cg += (kj > k); ce += (kj == k);
            }
            if (cg < r && r <= cg + ce) {
                sh_key = k;
                sh_m   = ce + 1u - (r - cg);
            }
        }
        __syncthreads();
    } else {
#pragma unroll
        for (int shift = 8; shift >= 0; shift -= 8) {
            s_hist[t] = 0;
            __syncthreads();
#pragma unroll
            for (int c = 0; c < 4; c++) {
                uint4 k4 = *(const uint4*)(s_k + (c * NT + t) * 4);
                unsigned int kk[4] = {k4.x, k4.y, k4.z, k4.w};
#pragma unroll
                for (int e = 0; e < 4; e++)
                    if ((kk[e] >> (shift + 8)) == prefix)
                        atomicAdd(&s_hist[(kk[e] >> shift) & 255u], 1u);
            }
            __syncthreads();
            select_bucket(r);
            prefix = (prefix << 8) | sh_sel;
            r = sh_r;
            if (t == 0 && shift == 0) { sh_key = prefix; sh_m = sh_h + 1u - sh_r; }
            __syncthreads();
        }
    }

    const float T = k2f(sh_key);
    const int   m = (int)sh_m;

    // ---- fused final pass: pos_loss + neg_sum ----
    const float thr   = T + 0.1f;
    const float lower = fmaxf(0.6f, pm) - 0.1f;
    float ploss = 0.f, ns = 0.f;
#pragma unroll
    for (int c = 0; c < 4; c++) {
        const int j0 = (c * NT + t) * 4;
        uint4  k4 = *(const uint4*)(s_k + j0);
        float4 p4 = *(const float4*)(s_p + j0);
        unsigned int kk[4] = {k4.x, k4.y, k4.z, k4.w};
        float        pp[4] = {p4.x, p4.y, p4.z, p4.w};
#pragma unroll
        for (int e = 0; e < 4; e++) {
            if (kk[e]) {
                const float v = k2f(kk[e]);
                if (v < T && v > lower) ns += v;
            }
            if (pp[e] > -1e29f && pp[e] < thr) ploss += 1.0f - pp[e];
        }
    }
#pragma unroll
    for (int o = 16; o > 0; o >>= 1) {
        ploss += __shfl_xor_sync(0xFFFFFFFFu, ploss, o);
        ns    += __shfl_xor_sync(0xFFFFFFFFu, ns, o);
    }
    if (lane == 0) { s_red[wid] = ploss; s_wtot[wid] = __float_as_uint(ns); }
    __syncthreads();

    if (t == 0) {
        float pl = 0.f, nss = 0.f;
#pragma unroll
        for (int w = 0; w < 8; w++) { pl += s_red[w]; nss += __uint_as_float(s_wtot[w]); }
        float loss = 0.f;
        if (pm > -1e29f) {
            loss = pl + nss;
            if (T > lower) loss += (float)m * T;
        }
        g_rowloss[i] = loss;
    }
}

// ---------------------------------------------------------------------------
__global__ void finalize_kernel(float* __restrict__ out) {
    __shared__ float s[1024];
    int t = threadIdx.x;
    float a = 0.f;
    for (int j = t; j < NROW; j += 1024) a += g_rowloss[j];
    s[t] = a; __syncthreads();
    for (int o = 512; o > 0; o >>= 1) { if (t < o) s[t] += s[t + o]; __syncthreads(); }
    if (t == 0) out[0] = s[0] / (float)NROW;
}

// ---------------------------------------------------------------------------
extern "C" void kernel_launch(void* const* d_in, const int* in_sizes, int n_in,
                              void* d_out, int out_size) {
    const float* emb   = (const float*)d_in[0];
    const int*   tgt32 = (const int*)d_in[1];
    float* out = (float*)d_out;

    cls_kernel<<<1, 1024>>>(tgt32);
    normalize_kernel<<<NROW, 256>>>(emb);
    gemm_kernel<<<528, 256>>>();
    row_loss_kernel<<<NROW, NT>>>();
    finalize_kernel<<<1, 1024>>>(out);
}